// round 3
// baseline (speedup 1.0000x reference)
#include <cuda_runtime.h>

#define D 64
#define MAXN 50048
#define MAXE 2000000

// Static scratch (no allocation allowed)
__device__ float g_hw[MAXN * D];       // h @ W  (12.8 MB, L2-resident)
__device__ int   g_cnt[MAXN];          // in-degree histogram (dst)
__device__ int   g_deg[MAXN];          // out-degree (src) for norm
__device__ int   g_fill[MAXN];         // running fill cursor per row
__device__ int   g_rowptr[MAXN + 1];   // CSR row pointers (by dst)
__device__ int   g_esrc[MAXE];         // CSR: src node per edge slot

// ---------------------------------------------------------------------------
// Zero the two histograms.
__global__ void zero_kernel(int n) {
    int i = blockIdx.x * blockDim.x + threadIdx.x;
    if (i < n) { g_cnt[i] = 0; g_deg[i] = 0; }
}

// ---------------------------------------------------------------------------
// hw = h @ W   (N x 64) @ (64 x 64). One block handles 16 rows.
__global__ __launch_bounds__(256) void gemm_kernel(const float* __restrict__ h,
                                                   const float* __restrict__ W,
                                                   int n) {
    __shared__ float sW[64][64];
    __shared__ float sh[16][64];
    int tid = threadIdx.x;
    int row0 = blockIdx.x * 16;

    for (int i = tid; i < 1024; i += 256)
        ((float4*)&sW[0][0])[i] = ((const float4*)W)[i];
    {
        int r = tid >> 4;
        int c4 = tid & 15;
        float4 v = make_float4(0.f, 0.f, 0.f, 0.f);
        if (row0 + r < n)
            v = ((const float4*)(h + (size_t)(row0 + r) * D))[c4];
        ((float4*)&sh[r][0])[c4] = v;
    }
    __syncthreads();

    int col = tid & 63;
    int rg  = tid >> 6;
    #pragma unroll
    for (int rr = 0; rr < 4; rr++) {
        int r = rg * 4 + rr;
        float acc = 0.f;
        #pragma unroll
        for (int k = 0; k < 64; k++)
            acc = fmaf(sh[r][k], sW[k][col], acc);
        int row = row0 + r;
        if (row < n)
            g_hw[(size_t)row * D + col] = acc;
    }
}

// ---------------------------------------------------------------------------
// Histograms: in-degree by dst (for CSR) and out-degree by src (for norm).
// Scalar int REDs, spread addresses -> cheap.
__global__ void hist_kernel(const int* __restrict__ src,
                            const int* __restrict__ dst, int nE) {
    int e = blockIdx.x * blockDim.x + threadIdx.x;
    if (e < nE) {
        atomicAdd(&g_cnt[dst[e]], 1);
        atomicAdd(&g_deg[src[e]], 1);
    }
}

// ---------------------------------------------------------------------------
// Exclusive prefix sum over g_cnt -> g_rowptr (and seed g_fill).
// Single block of 1024 threads; each thread owns a contiguous chunk.
__global__ __launch_bounds__(1024) void scan_kernel(int n) {
    __shared__ int sdata[1024];
    int tid = threadIdx.x;
    int chunk = (n + 1023) >> 10;
    int b = tid * chunk;
    int e = min(b + chunk, n);

    int s = 0;
    for (int i = b; i < e; i++) s += g_cnt[i];
    sdata[tid] = s;
    __syncthreads();

    // Hillis-Steele inclusive scan
    for (int off = 1; off < 1024; off <<= 1) {
        int v = (tid >= off) ? sdata[tid - off] : 0;
        __syncthreads();
        sdata[tid] += v;
        __syncthreads();
    }
    int run = (tid == 0) ? 0 : sdata[tid - 1];   // exclusive prefix
    for (int i = b; i < e; i++) {
        g_rowptr[i] = run;
        g_fill[i]   = run;
        run += g_cnt[i];
    }
    if (tid == 1023) g_rowptr[n] = run;          // total (last thread's chunk ends at n)
}

// ---------------------------------------------------------------------------
// Fill CSR: for each edge, claim a slot in its dst row and record src.
__global__ void fill_kernel(const int* __restrict__ src,
                            const int* __restrict__ dst, int nE) {
    int e = blockIdx.x * blockDim.x + threadIdx.x;
    if (e < nE) {
        int slot = atomicAdd(&g_fill[dst[e]], 1);
        g_esrc[slot] = src[e];
    }
}

// ---------------------------------------------------------------------------
// Gather + fused epilogue. 16 threads per output row (lane owns one float4
// column slot). Per batch of 16 edges: one coalesced index load, shfl
// broadcast, 16 independent 16B loads of L2-resident hw (MLP=16).
// Then out = relu(acc * rsqrt(deg) + bias) written once - no atomics.
__global__ __launch_bounds__(256) void gather_kernel(const float4* __restrict__ bias4,
                                                     float4* __restrict__ out,
                                                     int n) {
    int t = blockIdx.x * 256 + threadIdx.x;
    int row  = t >> 4;
    int lane = t & 15;
    if (row >= n) return;

    int start = g_rowptr[row];
    int end   = g_rowptr[row + 1];
    const float4* hw4 = (const float4*)g_hw;

    float4 acc = make_float4(0.f, 0.f, 0.f, 0.f);

    int j0 = start;
    // Full batches of 16 edges
    for (; j0 + 16 <= end; j0 += 16) {
        int idx = g_esrc[j0 + lane];
        #pragma unroll
        for (int jj = 0; jj < 16; jj++) {
            int s = __shfl_sync(0xFFFFFFFFu, idx, jj, 16);
            float4 v = hw4[(size_t)s * 16 + lane];
            acc.x += v.x; acc.y += v.y; acc.z += v.z; acc.w += v.w;
        }
    }
    // Tail
    int rem = end - j0;
    if (rem > 0) {
        int idx = (lane < rem) ? g_esrc[j0 + lane] : 0;
        for (int jj = 0; jj < rem; jj++) {
            int s = __shfl_sync(0xFFFFFFFFu, idx, jj, 16);
            float4 v = hw4[(size_t)s * 16 + lane];
            acc.x += v.x; acc.y += v.y; acc.z += v.z; acc.w += v.w;
        }
    }

    float nm = rsqrtf((float)g_deg[row]);
    float4 b = bias4[lane];
    float4 o;
    o.x = fmaxf(fmaf(acc.x, nm, b.x), 0.f);
    o.y = fmaxf(fmaf(acc.y, nm, b.y), 0.f);
    o.z = fmaxf(fmaf(acc.z, nm, b.z), 0.f);
    o.w = fmaxf(fmaf(acc.w, nm, b.w), 0.f);
    out[(size_t)row * 16 + lane] = o;
}

// ---------------------------------------------------------------------------
extern "C" void kernel_launch(void* const* d_in, const int* in_sizes, int n_in,
                              void* d_out, int out_size) {
    const float* h    = (const float*)d_in[0];
    const float* W    = (const float*)d_in[1];
    const float* bias = (const float*)d_in[2];
    const int*   src  = (const int*)d_in[3];
    const int*   dst  = (const int*)d_in[4];
    float* out = (float*)d_out;

    int n  = in_sizes[0] / D;     // 50000
    int nE = in_sizes[3];         // 1,650,000

    zero_kernel<<<(n + 255) / 256, 256>>>(n);
    gemm_kernel<<<(n + 15) / 16, 256>>>(h, W, n);
    hist_kernel<<<(nE + 255) / 256, 256>>>(src, dst, nE);
    scan_kernel<<<1, 1024>>>(n);
    fill_kernel<<<(nE + 255) / 256, 256>>>(src, dst, nE);

    int rows_threads = n * 16;
    gather_kernel<<<(rows_threads + 255) / 256, 256>>>((const float4*)bias,
                                                       (float4*)out, n);
}

// round 6
// speedup vs baseline: 1.6111x; 1.6111x over previous
#include <cuda_runtime.h>

#define D 64
#define MAXN 50048
#define MAXE 2000000
#define SCAN_B 256          // elements per scan block
#define MAX_SB 256          // max number of scan blocks (n <= 65536)

// Static scratch (no allocation allowed)
__device__ float g_hw[MAXN * D];       // h @ W  (12.8 MB, L2-resident)
__device__ int   g_cnt[MAXN];          // in-degree histogram (dst)
__device__ int   g_deg[MAXN];          // out-degree (src) for norm
__device__ int   g_fill[MAXN];         // running fill cursor per row
__device__ int   g_rowptr[MAXN + 1];   // CSR row pointers (by dst)
__device__ int   g_esrc[MAXE];         // CSR: src node per edge slot
__device__ int   g_bsum[MAX_SB];       // per-block partial sums
__device__ int   g_boff[MAX_SB];       // exclusive-scanned block offsets

// ---------------------------------------------------------------------------
__global__ void zero_kernel(int n) {
    int i = blockIdx.x * blockDim.x + threadIdx.x;
    if (i < n) { g_cnt[i] = 0; g_deg[i] = 0; }
}

// ---------------------------------------------------------------------------
// hw = h @ W   (N x 64) @ (64 x 64). One block handles 16 rows.
__global__ __launch_bounds__(256) void gemm_kernel(const float* __restrict__ h,
                                                   const float* __restrict__ W,
                                                   int n) {
    __shared__ float sW[64][64];
    __shared__ float sh[16][64];
    int tid = threadIdx.x;
    int row0 = blockIdx.x * 16;

    for (int i = tid; i < 1024; i += 256)
        ((float4*)&sW[0][0])[i] = ((const float4*)W)[i];
    {
        int r = tid >> 4;
        int c4 = tid & 15;
        float4 v = make_float4(0.f, 0.f, 0.f, 0.f);
        if (row0 + r < n)
            v = ((const float4*)(h + (size_t)(row0 + r) * D))[c4];
        ((float4*)&sh[r][0])[c4] = v;
    }
    __syncthreads();

    int col = tid & 63;
    int rg  = tid >> 6;
    #pragma unroll
    for (int rr = 0; rr < 4; rr++) {
        int r = rg * 4 + rr;
        float acc = 0.f;
        #pragma unroll
        for (int k = 0; k < 64; k++)
            acc = fmaf(sh[r][k], sW[k][col], acc);
        int row = row0 + r;
        if (row < n)
            g_hw[(size_t)row * D + col] = acc;
    }
}

// ---------------------------------------------------------------------------
// Histograms: in-degree by dst (CSR) and out-degree by src (norm).
__global__ void hist_kernel(const int* __restrict__ src,
                            const int* __restrict__ dst, int nE) {
    int e = blockIdx.x * blockDim.x + threadIdx.x;
    if (e < nE) {
        atomicAdd(&g_cnt[dst[e]], 1);
        atomicAdd(&g_deg[src[e]], 1);
    }
}

// ---------------------------------------------------------------------------
// Multi-block scan, phase A: block-local exclusive scan of g_cnt into
// g_rowptr (local offsets), block totals into g_bsum.
__global__ __launch_bounds__(SCAN_B) void scan_a_kernel(int n) {
    __shared__ int sd[SCAN_B];
    int tid = threadIdx.x;
    int i = blockIdx.x * SCAN_B + tid;
    int v = (i < n) ? g_cnt[i] : 0;
    sd[tid] = v;
    __syncthreads();
    for (int off = 1; off < SCAN_B; off <<= 1) {
        int t = (tid >= off) ? sd[tid - off] : 0;
        __syncthreads();
        sd[tid] += t;
        __syncthreads();
    }
    if (i < n) g_rowptr[i] = sd[tid] - v;        // local exclusive prefix
    if (tid == SCAN_B - 1) g_bsum[blockIdx.x] = sd[tid];
}

// Phase B: single block scans the (<=256) block sums exclusively.
__global__ __launch_bounds__(SCAN_B) void scan_b_kernel(int nb, int n) {
    __shared__ int sd[SCAN_B];
    int tid = threadIdx.x;
    int v = (tid < nb) ? g_bsum[tid] : 0;
    sd[tid] = v;
    __syncthreads();
    for (int off = 1; off < SCAN_B; off <<= 1) {
        int t = (tid >= off) ? sd[tid - off] : 0;
        __syncthreads();
        sd[tid] += t;
        __syncthreads();
    }
    if (tid < nb) g_boff[tid] = sd[tid] - v;     // exclusive block offsets
    if (tid == SCAN_B - 1) g_rowptr[n] = sd[tid];  // total edge count
}

// Phase C: add block offsets; seed fill cursors.
__global__ __launch_bounds__(SCAN_B) void scan_c_kernel(int n) {
    int i = blockIdx.x * SCAN_B + threadIdx.x;
    if (i < n) {
        int r = g_rowptr[i] + g_boff[blockIdx.x];
        g_rowptr[i] = r;
        g_fill[i]   = r;
    }
}

// ---------------------------------------------------------------------------
// Fill CSR: each edge claims a slot in its dst row, records src.
__global__ void fill_kernel(const int* __restrict__ src,
                            const int* __restrict__ dst, int nE) {
    int e = blockIdx.x * blockDim.x + threadIdx.x;
    if (e < nE) {
        int slot = atomicAdd(&g_fill[dst[e]], 1);
        g_esrc[slot] = src[e];
    }
}

// ---------------------------------------------------------------------------
// Gather + fused epilogue. 16 threads per output row (lane owns one float4
// column). Per batch of 16 edges: coalesced index load, shfl broadcast,
// 16 independent 16B loads of L2-resident hw. No atomics, single store.
__global__ __launch_bounds__(256) void gather_kernel(const float4* __restrict__ bias4,
                                                     float4* __restrict__ out,
                                                     int n) {
    int t = blockIdx.x * 256 + threadIdx.x;
    int row  = t >> 4;
    int lane = t & 15;
    if (row >= n) return;

    int start = g_rowptr[row];
    int end   = g_rowptr[row + 1];
    const float4* hw4 = (const float4*)g_hw;

    float4 acc = make_float4(0.f, 0.f, 0.f, 0.f);

    int j0 = start;
    for (; j0 + 16 <= end; j0 += 16) {
        int idx = g_esrc[j0 + lane];
        #pragma unroll
        for (int jj = 0; jj < 16; jj++) {
            int s = __shfl_sync(0xFFFFFFFFu, idx, jj, 16);
            float4 v = hw4[(size_t)s * 16 + lane];
            acc.x += v.x; acc.y += v.y; acc.z += v.z; acc.w += v.w;
        }
    }
    int rem = end - j0;
    if (rem > 0) {
        int idx = (lane < rem) ? g_esrc[j0 + lane] : 0;
        for (int jj = 0; jj < rem; jj++) {
            int s = __shfl_sync(0xFFFFFFFFu, idx, jj, 16);
            float4 v = hw4[(size_t)s * 16 + lane];
            acc.x += v.x; acc.y += v.y; acc.z += v.z; acc.w += v.w;
        }
    }

    float nm = rsqrtf((float)g_deg[row]);
    float4 b = bias4[lane];
    float4 o;
    o.x = fmaxf(fmaf(acc.x, nm, b.x), 0.f);
    o.y = fmaxf(fmaf(acc.y, nm, b.y), 0.f);
    o.z = fmaxf(fmaf(acc.z, nm, b.z), 0.f);
    o.w = fmaxf(fmaf(acc.w, nm, b.w), 0.f);
    out[(size_t)row * 16 + lane] = o;
}

// ---------------------------------------------------------------------------
extern "C" void kernel_launch(void* const* d_in, const int* in_sizes, int n_in,
                              void* d_out, int out_size) {
    const float* h    = (const float*)d_in[0];
    const float* W    = (const float*)d_in[1];
    const float* bias = (const float*)d_in[2];
    const int*   src  = (const int*)d_in[3];
    const int*   dst  = (const int*)d_in[4];
    float* out = (float*)d_out;

    int n  = in_sizes[0] / D;     // 50000
    int nE = in_sizes[3];         // 1,650,000

    int nb = (n + SCAN_B - 1) / SCAN_B;   // 196 <= MAX_SB

    zero_kernel<<<(n + 255) / 256, 256>>>(n);
    gemm_kernel<<<(n + 15) / 16, 256>>>(h, W, n);
    hist_kernel<<<(nE + 255) / 256, 256>>>(src, dst, nE);
    scan_a_kernel<<<nb, SCAN_B>>>(n);
    scan_b_kernel<<<1, SCAN_B>>>(nb, n);
    scan_c_kernel<<<nb, SCAN_B>>>(n);
    fill_kernel<<<(nE + 255) / 256, 256>>>(src, dst, nE);

    int rows_threads = n * 16;
    gather_kernel<<<(rows_threads + 255) / 256, 256>>>((const float4*)bias,
                                                       (float4*)out, n);
}

// round 7
// speedup vs baseline: 1.7594x; 1.0921x over previous
#include <cuda_runtime.h>

#define D 64
#define MAXN 50048
#define MAXE 2000000
#define SCAN_B 256          // elements per scan block
#define MAX_SB 256          // max number of scan blocks (n <= 65536)

// Static scratch (no allocation allowed)
__device__ float g_hw[MAXN * D];       // h @ W  (12.8 MB, L2-resident)
__device__ int   g_cnt[MAXN];          // in-degree histogram (dst)
__device__ int   g_deg[MAXN];          // out-degree (src) for norm
__device__ int   g_fill[MAXN];         // running fill cursor per row
__device__ int   g_rowptr[MAXN + 1];   // CSR row pointers (by dst)
__device__ int   g_esrc[MAXE];         // CSR: src node per edge slot
__device__ int   g_bsum[MAX_SB];       // per-block partial sums
__device__ int   g_boff[MAX_SB];       // exclusive-scanned block offsets

// ---------------------------------------------------------------------------
__global__ void zero_kernel(int n) {
    int i = blockIdx.x * blockDim.x + threadIdx.x;
    if (i < n) { g_cnt[i] = 0; g_deg[i] = 0; }
}

// ---------------------------------------------------------------------------
// hw = h @ W   (N x 64) @ (64 x 64). One block handles 16 rows.
__global__ __launch_bounds__(256) void gemm_kernel(const float* __restrict__ h,
                                                   const float* __restrict__ W,
                                                   int n) {
    __shared__ float sW[64][64];
    __shared__ float sh[16][64];
    int tid = threadIdx.x;
    int row0 = blockIdx.x * 16;

    for (int i = tid; i < 1024; i += 256)
        ((float4*)&sW[0][0])[i] = ((const float4*)W)[i];
    {
        int r = tid >> 4;
        int c4 = tid & 15;
        float4 v = make_float4(0.f, 0.f, 0.f, 0.f);
        if (row0 + r < n)
            v = ((const float4*)(h + (size_t)(row0 + r) * D))[c4];
        ((float4*)&sh[r][0])[c4] = v;
    }
    __syncthreads();

    int col = tid & 63;
    int rg  = tid >> 6;
    #pragma unroll
    for (int rr = 0; rr < 4; rr++) {
        int r = rg * 4 + rr;
        float acc = 0.f;
        #pragma unroll
        for (int k = 0; k < 64; k++)
            acc = fmaf(sh[r][k], sW[k][col], acc);
        int row = row0 + r;
        if (row < n)
            g_hw[(size_t)row * D + col] = acc;
    }
}

// ---------------------------------------------------------------------------
// In-degree histogram by dst (for CSR). Only reads dst.
__global__ void hist_kernel(const int* __restrict__ dst, int nE) {
    int e = blockIdx.x * blockDim.x + threadIdx.x;
    if (e < nE) atomicAdd(&g_cnt[dst[e]], 1);
}

// ---------------------------------------------------------------------------
// Multi-block scan, phase A: block-local exclusive scan of g_cnt into
// g_rowptr (local offsets), block totals into g_bsum.
__global__ __launch_bounds__(SCAN_B) void scan_a_kernel(int n) {
    __shared__ int sd[SCAN_B];
    int tid = threadIdx.x;
    int i = blockIdx.x * SCAN_B + tid;
    int v = (i < n) ? g_cnt[i] : 0;
    sd[tid] = v;
    __syncthreads();
    for (int off = 1; off < SCAN_B; off <<= 1) {
        int t = (tid >= off) ? sd[tid - off] : 0;
        __syncthreads();
        sd[tid] += t;
        __syncthreads();
    }
    if (i < n) g_rowptr[i] = sd[tid] - v;        // local exclusive prefix
    if (tid == SCAN_B - 1) g_bsum[blockIdx.x] = sd[tid];
}

// Phase B: single block scans the (<=256) block sums exclusively.
__global__ __launch_bounds__(SCAN_B) void scan_b_kernel(int nb, int n) {
    __shared__ int sd[SCAN_B];
    int tid = threadIdx.x;
    int v = (tid < nb) ? g_bsum[tid] : 0;
    sd[tid] = v;
    __syncthreads();
    for (int off = 1; off < SCAN_B; off <<= 1) {
        int t = (tid >= off) ? sd[tid - off] : 0;
        __syncthreads();
        sd[tid] += t;
        __syncthreads();
    }
    if (tid < nb) g_boff[tid] = sd[tid] - v;     // exclusive block offsets
    if (tid == SCAN_B - 1) g_rowptr[n] = sd[tid];  // total edge count
}

// Phase C: add block offsets; seed fill cursors.
__global__ __launch_bounds__(SCAN_B) void scan_c_kernel(int n) {
    int i = blockIdx.x * SCAN_B + threadIdx.x;
    if (i < n) {
        int r = g_rowptr[i] + g_boff[blockIdx.x];
        g_rowptr[i] = r;
        g_fill[i]   = r;
    }
}

// ---------------------------------------------------------------------------
// Fill CSR (slot claim by dst) + out-degree histogram by src (fused here
// since src is already loaded).
__global__ void fill_kernel(const int* __restrict__ src,
                            const int* __restrict__ dst, int nE) {
    int e = blockIdx.x * blockDim.x + threadIdx.x;
    if (e < nE) {
        int s = src[e];
        int slot = atomicAdd(&g_fill[dst[e]], 1);
        g_esrc[slot] = s;
        atomicAdd(&g_deg[s], 1);
    }
}

// ---------------------------------------------------------------------------
// Gather + fused epilogue. ONE WARP PER ROW: batches of 32 edges.
// Each lane covers edge (2*t + half) column (lane&15): half = lane>>4.
// Index load is one fully-coalesced 128B warp load per batch; loads are
// prefetched in groups of 8 float4 for MLP=8/lane. No intra-warp row
// imbalance. Epilogue (norm+bias+relu) fused; single store, no atomics.
__global__ __launch_bounds__(256) void gather_kernel(const float4* __restrict__ bias4,
                                                     float4* __restrict__ out,
                                                     int n) {
    int warp_id = (blockIdx.x * 256 + threadIdx.x) >> 5;
    int lane = threadIdx.x & 31;
    if (warp_id >= n) return;
    int row  = warp_id;
    int half = lane >> 4;      // which edge of the pair this lane handles
    int col  = lane & 15;      // float4 column owned by this lane

    int start = g_rowptr[row];
    int end   = g_rowptr[row + 1];
    const float4* hw4 = (const float4*)g_hw;

    float4 acc = make_float4(0.f, 0.f, 0.f, 0.f);

    int j0 = start;
    for (; j0 + 32 <= end; j0 += 32) {
        int idx = g_esrc[j0 + lane];           // coalesced 128B load
        float4 v[8];
        // steps 0..7 : edges 2t+half
        #pragma unroll
        for (int t = 0; t < 8; t++) {
            int s = __shfl_sync(0xFFFFFFFFu, idx, 2 * t + half);
            v[t] = hw4[(size_t)s * 16 + col];
        }
        #pragma unroll
        for (int t = 0; t < 8; t++) {
            acc.x += v[t].x; acc.y += v[t].y; acc.z += v[t].z; acc.w += v[t].w;
        }
        // steps 8..15
        #pragma unroll
        for (int t = 8; t < 16; t++) {
            int s = __shfl_sync(0xFFFFFFFFu, idx, 2 * t + half);
            v[t - 8] = hw4[(size_t)s * 16 + col];
        }
        #pragma unroll
        for (int t = 0; t < 8; t++) {
            acc.x += v[t].x; acc.y += v[t].y; acc.z += v[t].z; acc.w += v[t].w;
        }
    }
    // Tail: rem < 32 edges, processed in pairs.
    int rem = end - j0;
    if (rem > 0) {
        int idx = (lane < rem) ? g_esrc[j0 + lane] : 0;
        int nsteps = (rem + 1) >> 1;
        for (int t = 0; t < nsteps; t++) {
            int e = 2 * t + half;
            int srcl = (e < rem) ? e : (rem - 1);  // keep shfl source valid
            int s = __shfl_sync(0xFFFFFFFFu, idx, srcl);
            float4 v = hw4[(size_t)s * 16 + col];
            if (e < rem) {
                acc.x += v.x; acc.y += v.y; acc.z += v.z; acc.w += v.w;
            }
        }
    }

    // Combine the two half-warp partial sums: lane L gets lane L+16's acc.
    acc.x += __shfl_down_sync(0xFFFFFFFFu, acc.x, 16);
    acc.y += __shfl_down_sync(0xFFFFFFFFu, acc.y, 16);
    acc.z += __shfl_down_sync(0xFFFFFFFFu, acc.z, 16);
    acc.w += __shfl_down_sync(0xFFFFFFFFu, acc.w, 16);

    if (half == 0) {
        float nm = rsqrtf((float)g_deg[row]);
        float4 b = bias4[col];
        float4 o;
        o.x = fmaxf(fmaf(acc.x, nm, b.x), 0.f);
        o.y = fmaxf(fmaf(acc.y, nm, b.y), 0.f);
        o.z = fmaxf(fmaf(acc.z, nm, b.z), 0.f);
        o.w = fmaxf(fmaf(acc.w, nm, b.w), 0.f);
        out[(size_t)row * 16 + col] = o;
    }
}

// ---------------------------------------------------------------------------
extern "C" void kernel_launch(void* const* d_in, const int* in_sizes, int n_in,
                              void* d_out, int out_size) {
    const float* h    = (const float*)d_in[0];
    const float* W    = (const float*)d_in[1];
    const float* bias = (const float*)d_in[2];
    const int*   src  = (const int*)d_in[3];
    const int*   dst  = (const int*)d_in[4];
    float* out = (float*)d_out;

    int n  = in_sizes[0] / D;     // 50000
    int nE = in_sizes[3];         // 1,650,000

    int nb = (n + SCAN_B - 1) / SCAN_B;   // 196 <= MAX_SB

    zero_kernel<<<(n + 255) / 256, 256>>>(n);
    gemm_kernel<<<(n + 15) / 16, 256>>>(h, W, n);
    hist_kernel<<<(nE + 255) / 256, 256>>>(dst, nE);
    scan_a_kernel<<<nb, SCAN_B>>>(n);
    scan_b_kernel<<<1, SCAN_B>>>(nb, n);
    scan_c_kernel<<<nb, SCAN_B>>>(n);
    fill_kernel<<<(nE + 255) / 256, 256>>>(src, dst, nE);

    long long warps = n;                       // one warp per row
    int gblocks = (int)((warps * 32 + 255) / 256);
    gather_kernel<<<gblocks, 256>>>((const float4*)bias, (float4*)out, n);
}

// round 8
// speedup vs baseline: 1.8798x; 1.0684x over previous
#include <cuda_runtime.h>
#include <cuda_fp16.h>

#define D 64
#define MAXN 50048
#define MAXE 2000000
#define SCAN_B 256          // elements per scan block
#define MAX_SB 256          // max number of scan blocks (n <= 65536)

// Static scratch (no allocation allowed)
__device__ __half g_hwh[MAXN * D];     // h @ W in fp16  (6.4 MB, L2-resident)
__device__ int   g_cnt[MAXN];          // in-degree histogram (dst)
__device__ int   g_deg[MAXN];          // out-degree (src) for norm
__device__ int   g_fill[MAXN];         // running fill cursor per row
__device__ int   g_rowptr[MAXN + 1];   // CSR row pointers (by dst)
__device__ int   g_esrc[MAXE];         // CSR: src node per edge slot
__device__ int   g_bsum[MAX_SB];       // per-block partial sums
__device__ int   g_boff[MAX_SB];       // exclusive-scanned block offsets

// ---------------------------------------------------------------------------
// hw = h @ W   (N x 64) @ (64 x 64), stored as fp16. One block = 16 rows.
__global__ __launch_bounds__(256) void gemm_kernel(const float* __restrict__ h,
                                                   const float* __restrict__ W,
                                                   int n) {
    __shared__ float sW[64][64];
    __shared__ float sh[16][64];
    int tid = threadIdx.x;
    int row0 = blockIdx.x * 16;

    for (int i = tid; i < 1024; i += 256)
        ((float4*)&sW[0][0])[i] = ((const float4*)W)[i];
    {
        int r = tid >> 4;
        int c4 = tid & 15;
        float4 v = make_float4(0.f, 0.f, 0.f, 0.f);
        if (row0 + r < n)
            v = ((const float4*)(h + (size_t)(row0 + r) * D))[c4];
        ((float4*)&sh[r][0])[c4] = v;
    }
    __syncthreads();

    int col = tid & 63;
    int rg  = tid >> 6;
    #pragma unroll
    for (int rr = 0; rr < 4; rr++) {
        int r = rg * 4 + rr;
        float acc = 0.f;
        #pragma unroll
        for (int k = 0; k < 64; k++)
            acc = fmaf(sh[r][k], sW[k][col], acc);
        int row = row0 + r;
        if (row < n)
            g_hwh[(size_t)row * D + col] = __float2half_rn(acc);
    }
}

// ---------------------------------------------------------------------------
// In-degree histogram by dst (for CSR).
__global__ void hist_kernel(const int* __restrict__ dst, int nE) {
    int e = blockIdx.x * blockDim.x + threadIdx.x;
    if (e < nE) atomicAdd(&g_cnt[dst[e]], 1);
}

// ---------------------------------------------------------------------------
// Multi-block scan, phase A: block-local exclusive scan of g_cnt into
// g_rowptr (local offsets), block totals into g_bsum.
__global__ __launch_bounds__(SCAN_B) void scan_a_kernel(int n) {
    __shared__ int sd[SCAN_B];
    int tid = threadIdx.x;
    int i = blockIdx.x * SCAN_B + tid;
    int v = (i < n) ? g_cnt[i] : 0;
    sd[tid] = v;
    __syncthreads();
    for (int off = 1; off < SCAN_B; off <<= 1) {
        int t = (tid >= off) ? sd[tid - off] : 0;
        __syncthreads();
        sd[tid] += t;
        __syncthreads();
    }
    if (i < n) g_rowptr[i] = sd[tid] - v;        // local exclusive prefix
    if (tid == SCAN_B - 1) g_bsum[blockIdx.x] = sd[tid];
}

// Phase B: single block scans the (<=256) block sums exclusively.
__global__ __launch_bounds__(SCAN_B) void scan_b_kernel(int nb, int n) {
    __shared__ int sd[SCAN_B];
    int tid = threadIdx.x;
    int v = (tid < nb) ? g_bsum[tid] : 0;
    sd[tid] = v;
    __syncthreads();
    for (int off = 1; off < SCAN_B; off <<= 1) {
        int t = (tid >= off) ? sd[tid - off] : 0;
        __syncthreads();
        sd[tid] += t;
        __syncthreads();
    }
    if (tid < nb) g_boff[tid] = sd[tid] - v;     // exclusive block offsets
    if (tid == SCAN_B - 1) g_rowptr[n] = sd[tid];  // total edge count
}

// Phase C: add block offsets; seed fill cursors.
__global__ __launch_bounds__(SCAN_B) void scan_c_kernel(int n) {
    int i = blockIdx.x * SCAN_B + threadIdx.x;
    if (i < n) {
        int r = g_rowptr[i] + g_boff[blockIdx.x];
        g_rowptr[i] = r;
        g_fill[i]   = r;
    }
}

// ---------------------------------------------------------------------------
// Fill CSR (slot claim by dst) + out-degree histogram by src.
__global__ void fill_kernel(const int* __restrict__ src,
                            const int* __restrict__ dst, int nE) {
    int e = blockIdx.x * blockDim.x + threadIdx.x;
    if (e < nE) {
        int s = src[e];
        int slot = atomicAdd(&g_fill[dst[e]], 1);
        g_esrc[slot] = s;
        atomicAdd(&g_deg[s], 1);
    }
}

// ---------------------------------------------------------------------------
// Gather + fused epilogue. ONE WARP PER ROW: batches of 32 edges.
// hw rows are fp16 (128B); each lane loads 8B (uint2 = 4 halves), so a
// half-warp covers one full row coalesced. fp32 accumulation. Prefetch
// groups of 8 for MLP=8/lane. Epilogue fused, single store, no atomics.
__global__ __launch_bounds__(256) void gather_kernel(const float4* __restrict__ bias4,
                                                     float4* __restrict__ out,
                                                     int n) {
    int warp_id = (blockIdx.x * 256 + threadIdx.x) >> 5;
    int lane = threadIdx.x & 31;
    if (warp_id >= n) return;
    int row  = warp_id;
    int half_ = lane >> 4;     // which edge of the pair this lane handles
    int col  = lane & 15;      // uint2 (4-half) slot owned by this lane

    int start = g_rowptr[row];
    int end   = g_rowptr[row + 1];
    const uint2* hwv = (const uint2*)g_hwh;   // 16 uint2 per row

    float4 acc = make_float4(0.f, 0.f, 0.f, 0.f);

    int j0 = start;
    for (; j0 + 32 <= end; j0 += 32) {
        int idx = g_esrc[j0 + lane];           // coalesced 128B load
        uint2 v[8];
        #pragma unroll
        for (int t = 0; t < 8; t++) {
            int s = __shfl_sync(0xFFFFFFFFu, idx, 2 * t + half_);
            v[t] = hwv[(size_t)s * 16 + col];
        }
        #pragma unroll
        for (int t = 0; t < 8; t++) {
            float2 fa = __half22float2(*(__half2*)&v[t].x);
            float2 fb = __half22float2(*(__half2*)&v[t].y);
            acc.x += fa.x; acc.y += fa.y; acc.z += fb.x; acc.w += fb.y;
        }
        #pragma unroll
        for (int t = 8; t < 16; t++) {
            int s = __shfl_sync(0xFFFFFFFFu, idx, 2 * t + half_);
            v[t - 8] = hwv[(size_t)s * 16 + col];
        }
        #pragma unroll
        for (int t = 0; t < 8; t++) {
            float2 fa = __half22float2(*(__half2*)&v[t].x);
            float2 fb = __half22float2(*(__half2*)&v[t].y);
            acc.x += fa.x; acc.y += fa.y; acc.z += fb.x; acc.w += fb.y;
        }
    }
    // Tail: rem < 32 edges, processed in pairs.
    int rem = end - j0;
    if (rem > 0) {
        int idx = (lane < rem) ? g_esrc[j0 + lane] : 0;
        int nsteps = (rem + 1) >> 1;
        for (int t = 0; t < nsteps; t++) {
            int e = 2 * t + half_;
            int srcl = (e < rem) ? e : (rem - 1);  // keep shfl source valid
            int s = __shfl_sync(0xFFFFFFFFu, idx, srcl);
            uint2 v = hwv[(size_t)s * 16 + col];
            if (e < rem) {
                float2 fa = __half22float2(*(__half2*)&v.x);
                float2 fb = __half22float2(*(__half2*)&v.y);
                acc.x += fa.x; acc.y += fa.y; acc.z += fb.x; acc.w += fb.y;
            }
        }
    }

    // Combine the two half-warp partial sums.
    acc.x += __shfl_down_sync(0xFFFFFFFFu, acc.x, 16);
    acc.y += __shfl_down_sync(0xFFFFFFFFu, acc.y, 16);
    acc.z += __shfl_down_sync(0xFFFFFFFFu, acc.z, 16);
    acc.w += __shfl_down_sync(0xFFFFFFFFu, acc.w, 16);

    if (half_ == 0) {
        float nm = rsqrtf((float)g_deg[row]);
        float4 b = bias4[col];
        float4 o;
        o.x = fmaxf(fmaf(acc.x, nm, b.x), 0.f);
        o.y = fmaxf(fmaf(acc.y, nm, b.y), 0.f);
        o.z = fmaxf(fmaf(acc.z, nm, b.z), 0.f);
        o.w = fmaxf(fmaf(acc.w, nm, b.w), 0.f);
        out[(size_t)row * 16 + col] = o;
    }
}

// ---------------------------------------------------------------------------
extern "C" void kernel_launch(void* const* d_in, const int* in_sizes, int n_in,
                              void* d_out, int out_size) {
    const float* h    = (const float*)d_in[0];
    const float* W    = (const float*)d_in[1];
    const float* bias = (const float*)d_in[2];
    const int*   src  = (const int*)d_in[3];
    const int*   dst  = (const int*)d_in[4];
    float* out = (float*)d_out;

    int n  = in_sizes[0] / D;     // 50000
    int nE = in_sizes[3];         // 1,650,000

    int nb = (n + SCAN_B - 1) / SCAN_B;   // 196 <= MAX_SB

    // Zero histograms via graph memset nodes (no kernel launch needed).
    void* p_cnt = nullptr; void* p_deg = nullptr;
    cudaGetSymbolAddress(&p_cnt, g_cnt);
    cudaGetSymbolAddress(&p_deg, g_deg);
    cudaMemsetAsync(p_cnt, 0, (size_t)n * sizeof(int));
    cudaMemsetAsync(p_deg, 0, (size_t)n * sizeof(int));

    gemm_kernel<<<(n + 15) / 16, 256>>>(h, W, n);
    hist_kernel<<<(nE + 255) / 256, 256>>>(dst, nE);
    scan_a_kernel<<<nb, SCAN_B>>>(n);
    scan_b_kernel<<<1, SCAN_B>>>(nb, n);
    scan_c_kernel<<<nb, SCAN_B>>>(n);
    fill_kernel<<<(nE + 255) / 256, 256>>>(src, dst, nE);

    long long warps = n;                       // one warp per row
    int gblocks = (int)((warps * 32 + 255) / 256);
    gather_kernel<<<gblocks, 256>>>((const float4*)bias, (float4*)out, n);
}

// round 9
// speedup vs baseline: 1.9799x; 1.0533x over previous
#include <cuda_runtime.h>
#include <cuda_fp16.h>

#define D 64
#define MAXN 50048
#define MAXE 2000000
#define SCAN_B 256          // elements per scan block
#define MAX_SB 256          // max number of scan blocks (n <= 65536)

// Static scratch (no allocation allowed)
__device__ __half g_hwh[MAXN * D];     // h @ W in fp16  (6.4 MB, L2-resident)
__device__ int   g_cnt2[2 * MAXN];     // [0..MAXN): in-deg by dst, [MAXN..): out-deg by src
__device__ int   g_fill[MAXN];         // running fill cursor per row
__device__ int   g_rowptr[MAXN + 1];   // CSR row pointers (by dst)
__device__ int   g_esrc[MAXE];         // CSR: src node per edge slot
__device__ int   g_bsum[MAX_SB];       // per-block partial sums

// ---------------------------------------------------------------------------
// hw = h @ W   (N x 64) @ (64 x 64), stored as fp16. One block = 16 rows.
__global__ __launch_bounds__(256) void gemm_kernel(const float* __restrict__ h,
                                                   const float* __restrict__ W,
                                                   int n) {
    __shared__ float sW[64][64];
    __shared__ float sh[16][64];
    int tid = threadIdx.x;
    int row0 = blockIdx.x * 16;

    for (int i = tid; i < 1024; i += 256)
        ((float4*)&sW[0][0])[i] = ((const float4*)W)[i];
    {
        int r = tid >> 4;
        int c4 = tid & 15;
        float4 v = make_float4(0.f, 0.f, 0.f, 0.f);
        if (row0 + r < n)
            v = ((const float4*)(h + (size_t)(row0 + r) * D))[c4];
        ((float4*)&sh[r][0])[c4] = v;
    }
    __syncthreads();

    int col = tid & 63;
    int rg  = tid >> 6;
    #pragma unroll
    for (int rr = 0; rr < 4; rr++) {
        int r = rg * 4 + rr;
        float acc = 0.f;
        #pragma unroll
        for (int k = 0; k < 64; k++)
            acc = fmaf(sh[r][k], sW[k][col], acc);
        int row = row0 + r;
        if (row < n)
            g_hwh[(size_t)row * D + col] = __float2half_rn(acc);
    }
}

// ---------------------------------------------------------------------------
// In-degree histogram by dst (for CSR).
__global__ void hist_kernel(const int* __restrict__ dst, int nE) {
    int e = blockIdx.x * blockDim.x + threadIdx.x;
    if (e < nE) atomicAdd(&g_cnt2[dst[e]], 1);
}

// ---------------------------------------------------------------------------
// Scan phase A: block-local exclusive scan of g_cnt2[0..n) into g_rowptr
// (local offsets), block totals into g_bsum.
__global__ __launch_bounds__(SCAN_B) void scan_a_kernel(int n) {
    __shared__ int sd[SCAN_B];
    int tid = threadIdx.x;
    int i = blockIdx.x * SCAN_B + tid;
    int v = (i < n) ? g_cnt2[i] : 0;
    sd[tid] = v;
    __syncthreads();
    for (int off = 1; off < SCAN_B; off <<= 1) {
        int t = (tid >= off) ? sd[tid - off] : 0;
        __syncthreads();
        sd[tid] += t;
        __syncthreads();
    }
    if (i < n) g_rowptr[i] = sd[tid] - v;        // local exclusive prefix
    if (tid == SCAN_B - 1) g_bsum[blockIdx.x] = sd[tid];
}

// Scan phase C (fused B+C): every block redundantly scans the <=256 block
// sums in shared (trivial), takes its own exclusive offset, applies it to
// its 256 rowptr entries and seeds the fill cursors. Block 0 writes the
// total into g_rowptr[n].
__global__ __launch_bounds__(SCAN_B) void scan_c_kernel(int nb, int n) {
    __shared__ int sd[SCAN_B];
    int tid = threadIdx.x;
    int v = (tid < nb) ? g_bsum[tid] : 0;
    sd[tid] = v;
    __syncthreads();
    for (int off = 1; off < SCAN_B; off <<= 1) {
        int t = (tid >= off) ? sd[tid - off] : 0;
        __syncthreads();
        sd[tid] += t;
        __syncthreads();
    }
    // exclusive offset of this block = inclusive sum of blocks < blockIdx.x
    int boff = (blockIdx.x == 0) ? 0 : sd[blockIdx.x - 1];
    int i = blockIdx.x * SCAN_B + tid;
    if (i < n) {
        int r = g_rowptr[i] + boff;
        g_rowptr[i] = r;
        g_fill[i]   = r;
    }
    if (blockIdx.x == 0 && tid == 0) g_rowptr[n] = sd[nb - 1];  // total edges
}

// ---------------------------------------------------------------------------
// Fill CSR (slot claim by dst) + out-degree histogram by src.
__global__ void fill_kernel(const int* __restrict__ src,
                            const int* __restrict__ dst, int nE) {
    int e = blockIdx.x * blockDim.x + threadIdx.x;
    if (e < nE) {
        int s = src[e];
        int slot = atomicAdd(&g_fill[dst[e]], 1);
        g_esrc[slot] = s;
        atomicAdd(&g_cnt2[MAXN + s], 1);
    }
}

// ---------------------------------------------------------------------------
// Gather + fused epilogue. ONE WARP PER ROW: batches of 32 edges.
// hw rows are fp16 (128B); each lane loads 8B (uint2 = 4 halves); half-warp
// covers one row coalesced. fp32 accumulation, prefetch depth 8.
__global__ __launch_bounds__(256) void gather_kernel(const float4* __restrict__ bias4,
                                                     float4* __restrict__ out,
                                                     int n) {
    int warp_id = (blockIdx.x * 256 + threadIdx.x) >> 5;
    int lane = threadIdx.x & 31;
    if (warp_id >= n) return;
    int row  = warp_id;
    int half_ = lane >> 4;     // which edge of the pair this lane handles
    int col  = lane & 15;      // uint2 (4-half) slot owned by this lane

    int start = g_rowptr[row];
    int end   = g_rowptr[row + 1];
    const uint2* hwv = (const uint2*)g_hwh;   // 16 uint2 per row

    float4 acc = make_float4(0.f, 0.f, 0.f, 0.f);

    int j0 = start;
    for (; j0 + 32 <= end; j0 += 32) {
        int idx = g_esrc[j0 + lane];           // coalesced 128B load
        uint2 v[8];
        #pragma unroll
        for (int t = 0; t < 8; t++) {
            int s = __shfl_sync(0xFFFFFFFFu, idx, 2 * t + half_);
            v[t] = hwv[(size_t)s * 16 + col];
        }
        #pragma unroll
        for (int t = 0; t < 8; t++) {
            float2 fa = __half22float2(*(__half2*)&v[t].x);
            float2 fb = __half22float2(*(__half2*)&v[t].y);
            acc.x += fa.x; acc.y += fa.y; acc.z += fb.x; acc.w += fb.y;
        }
        #pragma unroll
        for (int t = 8; t < 16; t++) {
            int s = __shfl_sync(0xFFFFFFFFu, idx, 2 * t + half_);
            v[t - 8] = hwv[(size_t)s * 16 + col];
        }
        #pragma unroll
        for (int t = 0; t < 8; t++) {
            float2 fa = __half22float2(*(__half2*)&v[t].x);
            float2 fb = __half22float2(*(__half2*)&v[t].y);
            acc.x += fa.x; acc.y += fa.y; acc.z += fb.x; acc.w += fb.y;
        }
    }
    // Tail: rem < 32 edges, processed in pairs.
    int rem = end - j0;
    if (rem > 0) {
        int idx = (lane < rem) ? g_esrc[j0 + lane] : 0;
        int nsteps = (rem + 1) >> 1;
        for (int t = 0; t < nsteps; t++) {
            int e = 2 * t + half_;
            int srcl = (e < rem) ? e : (rem - 1);  // keep shfl source valid
            int s = __shfl_sync(0xFFFFFFFFu, idx, srcl);
            uint2 v = hwv[(size_t)s * 16 + col];
            if (e < rem) {
                float2 fa = __half22float2(*(__half2*)&v.x);
                float2 fb = __half22float2(*(__half2*)&v.y);
                acc.x += fa.x; acc.y += fa.y; acc.z += fb.x; acc.w += fb.y;
            }
        }
    }

    // Combine the two half-warp partial sums.
    acc.x += __shfl_down_sync(0xFFFFFFFFu, acc.x, 16);
    acc.y += __shfl_down_sync(0xFFFFFFFFu, acc.y, 16);
    acc.z += __shfl_down_sync(0xFFFFFFFFu, acc.z, 16);
    acc.w += __shfl_down_sync(0xFFFFFFFFu, acc.w, 16);

    if (half_ == 0) {
        float nm = rsqrtf((float)g_cnt2[MAXN + row]);   // out-degree
        float4 b = bias4[col];
        float4 o;
        o.x = fmaxf(fmaf(acc.x, nm, b.x), 0.f);
        o.y = fmaxf(fmaf(acc.y, nm, b.y), 0.f);
        o.z = fmaxf(fmaf(acc.z, nm, b.z), 0.f);
        o.w = fmaxf(fmaf(acc.w, nm, b.w), 0.f);
        out[(size_t)row * 16 + col] = o;
    }
}

// ---------------------------------------------------------------------------
extern "C" void kernel_launch(void* const* d_in, const int* in_sizes, int n_in,
                              void* d_out, int out_size) {
    const float* h    = (const float*)d_in[0];
    const float* W    = (const float*)d_in[1];
    const float* bias = (const float*)d_in[2];
    const int*   src  = (const int*)d_in[3];
    const int*   dst  = (const int*)d_in[4];
    float* out = (float*)d_out;

    int n  = in_sizes[0] / D;     // 50000
    int nE = in_sizes[3];         // 1,650,000

    int nb = (n + SCAN_B - 1) / SCAN_B;   // 196 <= MAX_SB

    // Static side stream + fork/join events (created on the first,
    // uncaptured correctness call; reused by capture).
    static cudaStream_t s2 = nullptr;
    static cudaEvent_t evFork = nullptr, evJoin = nullptr;
    if (!s2) {
        cudaStreamCreateWithFlags(&s2, cudaStreamNonBlocking);
        cudaEventCreateWithFlags(&evFork, cudaEventDisableTiming);
        cudaEventCreateWithFlags(&evJoin, cudaEventDisableTiming);
    }

    // Zero both histograms with one memset node.
    void* p_cnt2 = nullptr;
    cudaGetSymbolAddress(&p_cnt2, g_cnt2);
    cudaMemsetAsync(p_cnt2, 0, sizeof(int) * 2 * MAXN);

    // Fork: gemm on side stream (independent of the CSR build chain).
    cudaEventRecord(evFork, 0);
    cudaStreamWaitEvent(s2, evFork, 0);
    gemm_kernel<<<(n + 15) / 16, 256, 0, s2>>>(h, W, n);
    cudaEventRecord(evJoin, s2);

    // CSR build chain on main stream.
    hist_kernel<<<(nE + 255) / 256, 256>>>(dst, nE);
    scan_a_kernel<<<nb, SCAN_B>>>(n);
    scan_c_kernel<<<nb, SCAN_B>>>(nb, n);
    fill_kernel<<<(nE + 255) / 256, 256>>>(src, dst, nE);

    // Join, then gather (needs hw from gemm and CSR from fill).
    cudaStreamWaitEvent(0, evJoin, 0);
    int gblocks = (int)(((long long)n * 32 + 255) / 256);
    gather_kernel<<<gblocks, 256>>>((const float4*)bias, (float4*)out, n);
}